// round 14
// baseline (speedup 1.0000x reference)
#include <cuda_runtime.h>
#include <math.h>

// Problem shape (fixed by the dataset)
#define BB 16
#define CC 2
#define TT 2000
#define FF 257
#define NCHUNK 80
#define CL 25                    // TT / NCHUNK
#define GL 5                     // group length
#define NG 5                     // groups per chunk (NG*GL == CL)
#define NBC (BB * NCHUNK)        // scan work units = 1280
#define NTICKET (NBC * 3)        // scan + ch1 + res0 tickets = 3840
#define PLANE (TT * FF)
#define P4 (PLANE / 2)           // float4s per plane = 257000

// Scratch (no cudaMalloc allowed). Zero-init at load; self-reset per run.
__device__ float          g_agg[NBC * FF];   // chunk-local aggregates
__device__ volatile int   g_flag[NBC];       // aggregate published
__device__ volatile int   g_flag2[NBC];      // smooth chunk complete
__device__ unsigned int   g_vid;             // dynamic ticket counter
__device__ unsigned int   g_done;            // completion counter

__device__ __forceinline__ float sqrt_approx(float x) {
    float y; asm("sqrt.approx.f32 %0, %1;" : "=f"(y) : "f"(x)); return y;
}
__device__ __forceinline__ float rcp_approx(float x) {
    float y; asm("rcp.approx.f32 %0, %1;" : "=f"(y) : "f"(x)); return y;
}

__global__ void __launch_bounds__(288, 4)
fused_kernel(const float* __restrict__ in,
             const float* __restrict__ s1,
             const float* __restrict__ weights,
             const float* __restrict__ bias,
             const float* __restrict__ alpha_p,
             float* __restrict__ res,
             float* __restrict__ s_final,
             float* __restrict__ smooth) {
    __shared__ float sd[CL * FF];          // per-thread-column d stash (25.7KB)
    __shared__ unsigned int s_vid;
    __shared__ int s_last;
    int tid = threadIdx.x;

    if (tid == 0) { s_vid = atomicAdd(&g_vid, 1u); s_last = 0; }
    __syncthreads();
    unsigned int vid = s_vid;

    int role = vid % 3;                    // 0=scan, 1=ch1 stream, 2=res0
    int bc   = vid / 3;                    // (b, chunk) work unit
    int b    = bc / NCHUNK;
    int chunk = bc % NCHUNK;
    int t0   = chunk * CL;

    bool active = (tid < FF);
    int f = active ? tid : 0;              // clamp: lanes stay convergent

    if (role == 1) {
        // ========== CH1 STREAM: elementwise magnitude norm, flat float4 =====
        int j = chunk;                     // ticket index within b, 0..79
        int start = (j * P4) / NCHUNK;     // per-b float4 range (alternating size)
        int end   = ((j + 1) * P4) / NCHUNK;
        const float4* p1 = (const float4*)((const float2*)in +
                                           (size_t)(b * CC + 1) * PLANE);
        float4* r1 = (float4*)((float2*)res + (size_t)(b * CC + 1) * PLANE);
        const float* w1p = weights + FF;
        const float* b1p = bias + FF;

        for (int i = start + tid; i < end; i += 288) {
            int f0 = (2 * i) % FF;         // const-div -> mul/shift
            int f1 = (f0 + 1 == FF) ? 0 : f0 + 1;

            float4 x = __ldcs(&p1[i]);
            float w_0 = __ldg(&w1p[f0]);
            float w_1 = __ldg(&w1p[f1]);
            float b_0 = __ldg(&b1p[f0]);
            float b_1 = __ldg(&b1p[f1]);

            float m0 = sqrt_approx(x.x * x.x + x.y * x.y);
            float m1 = sqrt_approx(x.z * x.z + x.w * x.w);
            float i0 = w_0 * rcp_approx(m0 + 1e-8f);
            float i1 = w_1 * rcp_approx(m1 + 1e-8f);

            float4 o;
            o.x = fmaf(x.x, i0, b_0);
            o.y = fmaf(x.y, i0, b_0);
            o.z = fmaf(x.z, i1, b_1);
            o.w = fmaf(x.w, i1, b_1);
            __stcs(&r1[i], o);
        }
    } else if (role == 2) {
        // ========== RES0: elementwise given smooth (waits on scan ticket) ====
        while (g_flag2[bc] == 0) { }       // all threads spin; cheap L2 polls
        __threadfence();                    // acquire
        if (active) {
            float w0 = weights[0 * FF + f];
            float b0 = bias[0 * FF + f];
            const float2* p0 = (const float2*)in + (b * CC + 0) * PLANE + t0 * FF + f;
            const float*  sm = smooth + b * PLANE + t0 * FF + f;
            float2* r0 = (float2*)res + (b * CC + 0) * PLANE + t0 * FF + f;

            for (int tt = 0; tt < CL; tt += 5) {
                float2 x[5]; float s[5];
#pragma unroll
                for (int k = 0; k < 5; ++k) x[k] = __ldcs(&p0[(tt + k) * FF]);
#pragma unroll
                for (int k = 0; k < 5; ++k) s[k] = __ldcs(&sm[(tt + k) * FF]);
#pragma unroll
                for (int k = 0; k < 5; ++k) {
                    float inv = w0 * rcp_approx(s[k] + 1e-8f);
                    __stcs(&r0[(tt + k) * FF],
                           make_float2(fmaf(x[k].x, inv, b0),
                                       fmaf(x[k].y, inv, b0)));
                }
            }
        }
    } else {
        // ========== SCAN: ch0 EMA, d stashed in smem, writes smooth only =====
        float alpha = 1.0f / (1.0f + __expf(-alpha_p[f]));
        float r = 1.0f - alpha;
        float r2 = r * r, r4 = r2 * r2;
        float r5 = r4 * r;                 // r^GL
        float r25 = r5 * r5; r25 = r25 * r25 * r5;   // r^CL

        const float2* p = (const float2*)in + (b * CC + 0) * PLANE + t0 * FF + f;

        // ---- Phase 1: five independent group chains; stash d in smem ----
        float sg[NG] = {0.f, 0.f, 0.f, 0.f, 0.f};
        if (active) {
#pragma unroll
            for (int j = 0; j < GL; ++j) {
                float2 x[NG];
#pragma unroll
                for (int g = 0; g < NG; ++g) x[g] = p[(g * GL + j) * FF];
#pragma unroll
                for (int g = 0; g < NG; ++g) {
                    float d = x[g].x * x[g].x + x[g].y * x[g].y;
                    sd[(g * GL + j) * FF + tid] = d;   // own column, no sync needed
                    sg[g] = fmaf(r, sg[g], alpha * d);
                }
            }
            float s = sg[0];
#pragma unroll
            for (int g = 1; g < NG; ++g) s = fmaf(r5, s, sg[g]);
            g_agg[bc * FF + f] = s;
        }
        __syncthreads();
        __threadfence();
        if (tid == 0) g_flag[bc] = 1;      // release aggregate

        // ---- Lookback: parallel spin, then 8-wide batched fold ----
        if (tid < chunk) {
            int base = b * NCHUNK;
            while (g_flag[base + tid] == 0) { }
        }
        __syncthreads();
        __threadfence();                    // acquire

        float prefix = s1[b * FF + f];
        {
            const float* agg = g_agg + (b * NCHUNK) * FF + f;
            int c = 0;
            for (; c + 8 <= chunk; c += 8) {
                float a[8];
#pragma unroll
                for (int k = 0; k < 8; ++k) a[k] = agg[(c + k) * FF];
#pragma unroll
                for (int k = 0; k < 8; ++k) prefix = fmaf(r25, prefix, a[k]);
            }
            for (; c < chunk; ++c) prefix = fmaf(r25, prefix, agg[c * FF]);
        }

        // ---- Phase 3: replay chains from smem; write smooth only ----
        if (active) {
            float* sm = smooth + b * PLANE + t0 * FF + f;

            float sa[NG];
            sa[0] = prefix;
#pragma unroll
            for (int g = 1; g < NG; ++g) sa[g] = fmaf(r5, sa[g - 1], sg[g - 1]);

#pragma unroll
            for (int j = 0; j < GL; ++j) {
#pragma unroll
                for (int g = 0; g < NG; ++g) {
                    float d = sd[(g * GL + j) * FF + tid];
                    sa[g] = fmaf(r, sa[g], alpha * d);
                    sm[(g * GL + j) * FF] = sqrt_approx(sa[g]);  // keep in L2
                }
            }
            if (chunk == NCHUNK - 1) s_final[b * FF + f] = sa[NG - 1];
        }
        __syncthreads();
        __threadfence();
        if (tid == 0) g_flag2[bc] = 1;     // release smooth chunk
    }

    // ---- Self-reset for next graph replay (last block, parallelized) ----
    __syncthreads();
    if (tid == 0) {
        if (atomicAdd(&g_done, 1u) == NTICKET - 1) s_last = 1;
    }
    __syncthreads();
    if (s_last) {
        for (int i = tid; i < NBC; i += blockDim.x) { g_flag[i] = 0; g_flag2[i] = 0; }
        if (tid == 0) { g_vid = 0; g_done = 0; }
        __threadfence();
    }
}

extern "C" void kernel_launch(void* const* d_in, const int* in_sizes, int n_in,
                              void* d_out, int out_size) {
    // metadata order: input, s_1, weights, bias, alpha_param
    const float* in = (const float*)d_in[0];
    const float* s1 = (const float*)d_in[1];
    const float* w  = (const float*)d_in[2];
    const float* bi = (const float*)d_in[3];
    const float* ap = (const float*)d_in[4];

    float* out = (float*)d_out;
    float* res     = out;                                        // [B,C,T,F,2]
    float* s_final = out + (size_t)BB * CC * TT * FF * 2;        // [B,1,F,1]
    float* smooth  = s_final + (size_t)BB * FF;                  // [B,1,T,F,1]

    fused_kernel<<<NTICKET, 288>>>(in, s1, w, bi, ap, res, s_final, smooth);
}

// round 16
// speedup vs baseline: 1.6488x; 1.6488x over previous
#include <cuda_runtime.h>
#include <math.h>

// Problem shape (fixed by the dataset)
#define BB 16
#define CC 2
#define TT 2000
#define FF 257
#define NCHUNK 40
#define CL 50                    // TT / NCHUNK
#define GL 10                    // group length
#define NG 5                     // groups per chunk (NG*GL == CL)
#define NBC (BB * NCHUNK)        // scan work units = 640
#define NBLK (NBC * 2)           // + 640 stream blocks = 1280
#define PLANE (TT * FF)
#define CHUNK_V4 (CL * FF / 2)   // float4s per chunk plane-slice = 6425

// Scratch (no cudaMalloc allowed). Zero-init at load; self-reset per run.
__device__ float          g_agg[NBC * FF];   // chunk-local aggregates
__device__ volatile int   g_flag[NBC];       // publish flags per (b,chunk)
__device__ unsigned int   g_vid;             // dynamic block ticket
__device__ unsigned int   g_done;            // completion counter

__device__ __forceinline__ float rsqrt_approx(float x) {
    float y; asm("rsqrt.approx.f32 %0, %1;" : "=f"(y) : "f"(x)); return y;
}

__global__ void __launch_bounds__(288, 4)
fused_kernel(const float* __restrict__ in,
             const float* __restrict__ s1,
             const float* __restrict__ weights,
             const float* __restrict__ bias,
             const float* __restrict__ alpha_p,
             float* __restrict__ res,
             float* __restrict__ s_final,
             float* __restrict__ smooth) {
    __shared__ unsigned int s_vid;
    __shared__ int s_last;
    if (threadIdx.x == 0) { s_vid = atomicAdd(&g_vid, 1u); s_last = 0; }
    __syncthreads();
    unsigned int vid = s_vid;

    int is_stream = vid & 1;         // interleave roles so both kinds co-reside
    int bc    = vid >> 1;            // (b, chunk) work unit, 0..639
    int b     = bc / NCHUNK;
    int chunk = bc % NCHUNK;
    int t0    = chunk * CL;
    int tid   = threadIdx.x;

    if (is_stream) {
        // ============ STREAM ROLE: ch1 elementwise, flat float4 =============
        const float4* p1 = (const float4*)((const float2*)in +
                                           (size_t)(b * CC + 1) * PLANE + t0 * FF);
        float4* r1 = (float4*)((float2*)res +
                               (size_t)(b * CC + 1) * PLANE + t0 * FF);
        int gbase = t0 * FF;                      // complex idx of chunk start
        const float* w1p = weights + FF;
        const float* b1p = bias + FF;

        for (int i = tid; i < CHUNK_V4; i += 288) {
            int g = gbase + 2 * i;                // complex idx within plane
            int f0 = g % FF;                      // const-div -> mul/shift
            int f1 = (f0 + 1 == FF) ? 0 : f0 + 1;

            float4 x = __ldcs(&p1[i]);
            float w_0 = __ldg(&w1p[f0]);
            float w_1 = __ldg(&w1p[f1]);
            float b_0 = __ldg(&b1p[f0]);
            float b_1 = __ldg(&b1p[f1]);

            // 1/(sqrt(d)+eps) ~= t*(1-eps*t), t=rsqrt(d): one MUFU per element
            float d0 = x.x * x.x + x.y * x.y;
            float d1 = x.z * x.z + x.w * x.w;
            float ta = rsqrt_approx(fmaxf(d0, 1e-12f));
            float tb = rsqrt_approx(fmaxf(d1, 1e-12f));
            float i0 = w_0 * ta * fmaf(-1e-8f, ta, 1.0f);
            float i1 = w_1 * tb * fmaf(-1e-8f, tb, 1.0f);

            float4 o;
            o.x = fmaf(x.x, i0, b_0);
            o.y = fmaf(x.y, i0, b_0);
            o.z = fmaf(x.z, i1, b_1);
            o.w = fmaf(x.w, i1, b_1);
            __stcs(&r1[i], o);
        }
    } else {
        // ============ SCAN ROLE: ch0, affine-group decomposition =============
        bool active = (tid < FF);
        int f = active ? tid : 0;    // clamp: lanes stay convergent

        float alpha = 1.0f / (1.0f + __expf(-alpha_p[f]));
        float r = 1.0f - alpha;
        float r2 = r * r, r4 = r2 * r2, r8 = r4 * r4;
        float r10 = r8 * r2;

        const float2* in0 = (const float2*)in + (b * CC + 0) * PLANE;
        const float2* p = in0 + t0 * FF + f;

        // ---- Phase 1: five independent group-aggregate chains ----
        float sg[NG] = {0.f, 0.f, 0.f, 0.f, 0.f};
        if (active) {
#pragma unroll
            for (int j = 0; j < GL; ++j) {
                float2 x[NG];
#pragma unroll
                for (int g = 0; g < NG; ++g) x[g] = p[(g * GL + j) * FF];
#pragma unroll
                for (int g = 0; g < NG; ++g) {
                    float d = x[g].x * x[g].x + x[g].y * x[g].y;
                    sg[g] = fmaf(r, sg[g], alpha * d);
                }
            }
            float s = sg[0];
#pragma unroll
            for (int g = 1; g < NG; ++g) s = fmaf(r10, s, sg[g]);
            g_agg[bc * FF + f] = s;
        }
        __syncthreads();
        __threadfence();
        if (threadIdx.x == 0) g_flag[bc] = 1;      // release

        // ---- Prefetch phase-3's first batch (independent of prefix) ----
        float2 x0[NG];
        if (active) {
#pragma unroll
            for (int g = 0; g < NG; ++g) x0[g] = __ldcs(&p[(g * GL) * FF]);
        }

        // ---- Lookback: parallel spin, then fold ----
        if (threadIdx.x < chunk) {
            int base = b * NCHUNK;
            while (g_flag[base + threadIdx.x] == 0) { }
        }
        __syncthreads();
        __threadfence();                            // acquire

        float r50 = r10 * r10; r50 = r50 * r50 * r10;   // r^CL

        float prefix = s1[b * FF + f];
        {
            const float* agg = g_agg + (b * NCHUNK) * FF + f;
            for (int c = 0; c < chunk; ++c)
                prefix = fmaf(r50, prefix, agg[c * FF]);
        }

        // ---- Phase 3: five concurrent scan chains with group prefixes ----
        if (active) {
            float w0 = weights[0 * FF + f];
            float b0 = bias[0 * FF + f];

            float2* r0 = (float2*)res + (b * CC + 0) * PLANE + t0 * FF + f;
            float*  sm = smooth + b * PLANE + t0 * FF + f;

            // group-entry states: P0 = prefix; P_{g+1} = r10*P_g + B_g
            float sa[NG];
            sa[0] = prefix;
#pragma unroll
            for (int g = 1; g < NG; ++g) sa[g] = fmaf(r10, sa[g - 1], sg[g - 1]);

#pragma unroll
            for (int j = 0; j < GL; ++j) {
                float2 x[NG];
                if (j == 0) {
#pragma unroll
                    for (int g = 0; g < NG; ++g) x[g] = x0[g];
                } else {
#pragma unroll
                    for (int g = 0; g < NG; ++g) x[g] = __ldcs(&p[(g * GL + j) * FF]);
                }
#pragma unroll
                for (int g = 0; g < NG; ++g) {
                    float d = x[g].x * x[g].x + x[g].y * x[g].y;
                    sa[g] = fmaf(r, sa[g], alpha * d);
                    // one rsqrt gives both smooth and the normalizer:
                    // sm = s*t (= sqrt(s)), inv = w0*t*(1-eps*t)
                    float t = rsqrt_approx(fmaxf(sa[g], 1e-12f));
                    float smv = sa[g] * t;
                    int off = (g * GL + j) * FF;
                    __stcs(&sm[off], smv);
                    float inv = w0 * t * fmaf(-1e-8f, t, 1.0f);
                    __stcs(&r0[off], make_float2(fmaf(x[g].x, inv, b0),
                                                 fmaf(x[g].y, inv, b0)));
                }
            }
            if (chunk == NCHUNK - 1) s_final[b * FF + f] = sa[NG - 1];
        }
    }

    // ---- Self-reset for next graph replay (parallelized) ----
    __syncthreads();
    if (threadIdx.x == 0) {
        if (atomicAdd(&g_done, 1u) == NBLK - 1) s_last = 1;
    }
    __syncthreads();
    if (s_last) {
        for (int i = threadIdx.x; i < NBC; i += blockDim.x) g_flag[i] = 0;
        if (threadIdx.x == 0) { g_vid = 0; g_done = 0; }
        __threadfence();
    }
}

extern "C" void kernel_launch(void* const* d_in, const int* in_sizes, int n_in,
                              void* d_out, int out_size) {
    // metadata order: input, s_1, weights, bias, alpha_param
    const float* in = (const float*)d_in[0];
    const float* s1 = (const float*)d_in[1];
    const float* w  = (const float*)d_in[2];
    const float* bi = (const float*)d_in[3];
    const float* ap = (const float*)d_in[4];

    float* out = (float*)d_out;
    float* res     = out;                                        // [B,C,T,F,2]
    float* s_final = out + (size_t)BB * CC * TT * FF * 2;        // [B,1,F,1]
    float* smooth  = s_final + (size_t)BB * FF;                  // [B,1,T,F,1]

    fused_kernel<<<NBLK, 288>>>(in, s1, w, bi, ap, res, s_final, smooth);
}

// round 17
// speedup vs baseline: 1.7253x; 1.0464x over previous
#include <cuda_runtime.h>
#include <math.h>

// Problem shape (fixed by the dataset)
#define BB 16
#define CC 2
#define TT 2000
#define FF 257
#define NCHUNK 40
#define CL 50                    // TT / NCHUNK
#define GL 10                    // group length
#define NG 5                     // groups per chunk (NG*GL == CL)
#define NBC (BB * NCHUNK)        // scan work units = 640
#define NBLK (NBC * 2)           // + 640 stream blocks = 1280
#define PLANE (TT * FF)
#define CHUNK_V4 (CL * FF / 2)   // float4s per chunk plane-slice = 6425

// Scratch (no cudaMalloc allowed). Zero-init at load; self-reset per run.
__device__ float          g_agg[NBC * FF];   // chunk-local aggregates
__device__ volatile int   g_flag[NBC];       // publish flags per (b,chunk)
__device__ unsigned int   g_vid;             // dynamic block ticket
__device__ unsigned int   g_done;            // completion counter

__device__ __forceinline__ float rsqrt_approx(float x) {
    float y; asm("rsqrt.approx.f32 %0, %1;" : "=f"(y) : "f"(x)); return y;
}

__global__ void __launch_bounds__(288, 4)
fused_kernel(const float* __restrict__ in,
             const float* __restrict__ s1,
             const float* __restrict__ weights,
             const float* __restrict__ bias,
             const float* __restrict__ alpha_p,
             float* __restrict__ res,
             float* __restrict__ s_final,
             float* __restrict__ smooth) {
    __shared__ unsigned int s_vid;
    __shared__ int s_last;
    if (threadIdx.x == 0) { s_vid = atomicAdd(&g_vid, 1u); s_last = 0; }
    __syncthreads();
    unsigned int vid = s_vid;

    int is_stream = vid & 1;         // interleave roles so both kinds co-reside
    int bc    = vid >> 1;            // (b, chunk) work unit, 0..639
    int b     = bc / NCHUNK;
    int chunk = bc % NCHUNK;
    int t0    = chunk * CL;
    int tid   = threadIdx.x;

    if (is_stream) {
        // ============ STREAM ROLE: ch1 elementwise, 4x-batched float4 =======
        const float4* p1 = (const float4*)((const float2*)in +
                                           (size_t)(b * CC + 1) * PLANE + t0 * FF);
        float4* r1 = (float4*)((float2*)res +
                               (size_t)(b * CC + 1) * PLANE + t0 * FF);
        int gbase = t0 * FF;                      // complex idx of chunk start
        const float* w1p = weights + FF;
        const float* b1p = bias + FF;

        int i = tid;
        // main: 4 iterations in flight (16 loads + 8 param loads before compute)
        for (; i + 3 * 288 < CHUNK_V4; i += 4 * 288) {
            float4 x[4];
            float wA[4], wB[4], bA[4], bB[4];
            int fA[4], fB[4];
#pragma unroll
            for (int k = 0; k < 4; ++k) x[k] = __ldcs(&p1[i + k * 288]);
#pragma unroll
            for (int k = 0; k < 4; ++k) {
                int g = gbase + 2 * (i + k * 288);
                fA[k] = g % FF;                   // const-div -> mul/shift
                fB[k] = (fA[k] + 1 == FF) ? 0 : fA[k] + 1;
            }
#pragma unroll
            for (int k = 0; k < 4; ++k) {
                wA[k] = __ldg(&w1p[fA[k]]); wB[k] = __ldg(&w1p[fB[k]]);
                bA[k] = __ldg(&b1p[fA[k]]); bB[k] = __ldg(&b1p[fB[k]]);
            }
#pragma unroll
            for (int k = 0; k < 4; ++k) {
                float d0 = x[k].x * x[k].x + x[k].y * x[k].y;
                float d1 = x[k].z * x[k].z + x[k].w * x[k].w;
                float ta = rsqrt_approx(fmaxf(d0, 1e-12f));
                float tb = rsqrt_approx(fmaxf(d1, 1e-12f));
                float i0 = wA[k] * ta * fmaf(-1e-8f, ta, 1.0f);
                float i1 = wB[k] * tb * fmaf(-1e-8f, tb, 1.0f);
                float4 o;
                o.x = fmaf(x[k].x, i0, bA[k]);
                o.y = fmaf(x[k].y, i0, bA[k]);
                o.z = fmaf(x[k].z, i1, bB[k]);
                o.w = fmaf(x[k].w, i1, bB[k]);
                __stcs(&r1[i + k * 288], o);
            }
        }
        // tail
        for (; i < CHUNK_V4; i += 288) {
            int g = gbase + 2 * i;
            int f0 = g % FF;
            int f1 = (f0 + 1 == FF) ? 0 : f0 + 1;
            float4 x = __ldcs(&p1[i]);
            float w_0 = __ldg(&w1p[f0]);
            float w_1 = __ldg(&w1p[f1]);
            float b_0 = __ldg(&b1p[f0]);
            float b_1 = __ldg(&b1p[f1]);
            float d0 = x.x * x.x + x.y * x.y;
            float d1 = x.z * x.z + x.w * x.w;
            float ta = rsqrt_approx(fmaxf(d0, 1e-12f));
            float tb = rsqrt_approx(fmaxf(d1, 1e-12f));
            float i0 = w_0 * ta * fmaf(-1e-8f, ta, 1.0f);
            float i1 = w_1 * tb * fmaf(-1e-8f, tb, 1.0f);
            float4 o;
            o.x = fmaf(x.x, i0, b_0);
            o.y = fmaf(x.y, i0, b_0);
            o.z = fmaf(x.z, i1, b_1);
            o.w = fmaf(x.w, i1, b_1);
            __stcs(&r1[i], o);
        }
    } else {
        // ============ SCAN ROLE: ch0, affine-group decomposition =============
        bool active = (tid < FF);
        int f = active ? tid : 0;    // clamp: lanes stay convergent

        float alpha = 1.0f / (1.0f + __expf(-alpha_p[f]));
        float r = 1.0f - alpha;
        float r2 = r * r, r4 = r2 * r2, r8 = r4 * r4;
        float r10 = r8 * r2;

        const float2* in0 = (const float2*)in + (b * CC + 0) * PLANE;
        const float2* p = in0 + t0 * FF + f;

        // ---- Phase 1: five independent group-aggregate chains ----
        float sg[NG] = {0.f, 0.f, 0.f, 0.f, 0.f};
        if (active) {
#pragma unroll
            for (int j = 0; j < GL; ++j) {
                float2 x[NG];
#pragma unroll
                for (int g = 0; g < NG; ++g) x[g] = p[(g * GL + j) * FF];
#pragma unroll
                for (int g = 0; g < NG; ++g) {
                    float d = x[g].x * x[g].x + x[g].y * x[g].y;
                    sg[g] = fmaf(r, sg[g], alpha * d);
                }
            }
            float s = sg[0];
#pragma unroll
            for (int g = 1; g < NG; ++g) s = fmaf(r10, s, sg[g]);
            g_agg[bc * FF + f] = s;
        }
        __syncthreads();
        __threadfence();
        if (threadIdx.x == 0) g_flag[bc] = 1;      // release

        // ---- Prefetch phase-3's first batch (independent of prefix) ----
        float2 x0[NG];
        if (active) {
#pragma unroll
            for (int g = 0; g < NG; ++g) x0[g] = __ldcs(&p[(g * GL) * FF]);
        }

        // ---- Lookback: parallel spin, then fold ----
        if (threadIdx.x < chunk) {
            int base = b * NCHUNK;
            while (g_flag[base + threadIdx.x] == 0) { }
        }
        __syncthreads();
        __threadfence();                            // acquire

        float r50 = r10 * r10; r50 = r50 * r50 * r10;   // r^CL

        float prefix = s1[b * FF + f];
        {
            const float* agg = g_agg + (b * NCHUNK) * FF + f;
            for (int c = 0; c < chunk; ++c)
                prefix = fmaf(r50, prefix, agg[c * FF]);
        }

        // ---- Phase 3: five concurrent scan chains with group prefixes ----
        if (active) {
            float w0 = weights[0 * FF + f];
            float b0 = bias[0 * FF + f];

            float2* r0 = (float2*)res + (b * CC + 0) * PLANE + t0 * FF + f;
            float*  sm = smooth + b * PLANE + t0 * FF + f;

            // group-entry states: P0 = prefix; P_{g+1} = r10*P_g + B_g
            float sa[NG];
            sa[0] = prefix;
#pragma unroll
            for (int g = 1; g < NG; ++g) sa[g] = fmaf(r10, sa[g - 1], sg[g - 1]);

#pragma unroll
            for (int j = 0; j < GL; ++j) {
                float2 x[NG];
                if (j == 0) {
#pragma unroll
                    for (int g = 0; g < NG; ++g) x[g] = x0[g];
                } else {
#pragma unroll
                    for (int g = 0; g < NG; ++g) x[g] = __ldcs(&p[(g * GL + j) * FF]);
                }
#pragma unroll
                for (int g = 0; g < NG; ++g) {
                    float d = x[g].x * x[g].x + x[g].y * x[g].y;
                    sa[g] = fmaf(r, sa[g], alpha * d);
                    // one rsqrt gives both smooth and the normalizer:
                    // sm = s*t (= sqrt(s)), inv = w0*t*(1-eps*t)
                    float t = rsqrt_approx(fmaxf(sa[g], 1e-12f));
                    float smv = sa[g] * t;
                    int off = (g * GL + j) * FF;
                    __stcs(&sm[off], smv);
                    float inv = w0 * t * fmaf(-1e-8f, t, 1.0f);
                    __stcs(&r0[off], make_float2(fmaf(x[g].x, inv, b0),
                                                 fmaf(x[g].y, inv, b0)));
                }
            }
            if (chunk == NCHUNK - 1) s_final[b * FF + f] = sa[NG - 1];
        }
    }

    // ---- Self-reset for next graph replay (parallelized) ----
    __syncthreads();
    if (threadIdx.x == 0) {
        if (atomicAdd(&g_done, 1u) == NBLK - 1) s_last = 1;
    }
    __syncthreads();
    if (s_last) {
        for (int i = threadIdx.x; i < NBC; i += blockDim.x) g_flag[i] = 0;
        if (threadIdx.x == 0) { g_vid = 0; g_done = 0; }
        __threadfence();
    }
}

extern "C" void kernel_launch(void* const* d_in, const int* in_sizes, int n_in,
                              void* d_out, int out_size) {
    // metadata order: input, s_1, weights, bias, alpha_param
    const float* in = (const float*)d_in[0];
    const float* s1 = (const float*)d_in[1];
    const float* w  = (const float*)d_in[2];
    const float* bi = (const float*)d_in[3];
    const float* ap = (const float*)d_in[4];

    float* out = (float*)d_out;
    float* res     = out;                                        // [B,C,T,F,2]
    float* s_final = out + (size_t)BB * CC * TT * FF * 2;        // [B,1,F,1]
    float* smooth  = s_final + (size_t)BB * FF;                  // [B,1,T,F,1]

    fused_kernel<<<NBLK, 288>>>(in, s1, w, bi, ap, res, s_final, smooth);
}